// round 1
// baseline (speedup 1.0000x reference)
#include <cuda_runtime.h>
#include <float.h>

// Problem constants (fixed by the reference: B=4, M=1024, N=32768)
#define BB 4
#define MM 1024
#define NN 32768

#define KM 16                 // keypoints per block (register-resident)
#define NCHUNKS 4             // split of N across blocks
#define NC (NN / NCHUNKS)     // 8192 points per chunk
#define NTHREADS 256
#define ITERS (NC / NTHREADS) // 32 points per thread

// Scratch (no cudaMalloc allowed): packed points + partial mins
__device__ float4 g_pk[BB * NN];                 // [b][n] = (px,py,pz, 0.5*|p|^2)  (2 MB)
__device__ float  g_partial[BB * MM * NCHUNKS];  // partial mins of (hp2 - k.p)

// --- Kernel 1: pack pc [B,3,N] -> float4 (x,y,z, 0.5*(x^2+y^2+z^2)) ---
__global__ void pack_kernel(const float* __restrict__ pc) {
    int idx = blockIdx.x * blockDim.x + threadIdx.x;
    if (idx >= BB * NN) return;
    int b = idx / NN, n = idx - b * NN;
    const float* base = pc + (size_t)b * 3 * NN;
    float x = base[n];
    float y = base[NN + n];
    float z = base[2 * NN + n];
    g_pk[idx] = make_float4(x, y, z, 0.5f * (x * x + y * y + z * z));
}

// --- Kernel 2: per (b, m-group, n-chunk) block: min over its points ---
__global__ void __launch_bounds__(NTHREADS, 2)
min_kernel(const float* __restrict__ kpt) {
    const int nchunk = blockIdx.x;
    const int mg     = blockIdx.y;
    const int b      = blockIdx.z;
    const int m0     = mg * KM;
    const int t      = threadIdx.x;

    // Load KM keypoints into registers (broadcast across threads).
    const float* kb = kpt + (size_t)b * 3 * MM;
    float kx[KM], ky[KM], kz[KM], mn[KM];
#pragma unroll
    for (int j = 0; j < KM; j++) {
        kx[j] = kb[m0 + j];
        ky[j] = kb[MM + m0 + j];
        kz[j] = kb[2 * MM + m0 + j];
        mn[j] = FLT_MAX;
    }

    const float4* __restrict__ pk = g_pk + (size_t)b * NN + (size_t)nchunk * NC;

#pragma unroll 4
    for (int i = 0; i < ITERS; i++) {
        float4 p = pk[i * NTHREADS + t];
#pragma unroll
        for (int j = 0; j < KM; j++) {
            // hp2 - kx*px - ky*py - kz*pz  (3 FFMA with free neg modifiers)
            float v = fmaf(-kx[j], p.x,
                      fmaf(-ky[j], p.y,
                      fmaf(-kz[j], p.z, p.w)));
            mn[j] = fminf(mn[j], v);
        }
    }

    // Warp-level min reduce for each keypoint.
#pragma unroll
    for (int j = 0; j < KM; j++) {
#pragma unroll
        for (int off = 16; off; off >>= 1)
            mn[j] = fminf(mn[j], __shfl_xor_sync(0xffffffffu, mn[j], off));
    }

    __shared__ float s[NTHREADS / 32][KM];
    int warp = t >> 5, lane = t & 31;
    if (lane == 0) {
#pragma unroll
        for (int j = 0; j < KM; j++) s[warp][j] = mn[j];
    }
    __syncthreads();

    if (t < KM) {
        float v = s[0][t];
#pragma unroll
        for (int w = 1; w < NTHREADS / 32; w++) v = fminf(v, s[w][t]);
        g_partial[(size_t)(b * MM + m0 + t) * NCHUNKS + nchunk] = v;
    }
}

// --- Kernel 3: combine chunks, d2 = k2 + 2*min, sqrt, mean over all (b,m) ---
__global__ void __launch_bounds__(1024)
reduce_kernel(const float* __restrict__ kpt, float* __restrict__ out) {
    const int t = threadIdx.x;
    float sum = 0.0f;
    for (int m = t; m < BB * MM; m += 1024) {
        int b = m / MM, mm = m - b * MM;
        float v = g_partial[(size_t)m * NCHUNKS];
#pragma unroll
        for (int c = 1; c < NCHUNKS; c++)
            v = fminf(v, g_partial[(size_t)m * NCHUNKS + c]);
        const float* kb = kpt + (size_t)b * 3 * MM;
        float x = kb[mm], y = kb[MM + mm], z = kb[2 * MM + mm];
        float k2 = x * x + y * y + z * z;
        float d2 = fmaxf(fmaf(2.0f, v, k2), 0.0f);
        sum += sqrtf(d2);
    }
    __shared__ float ss[1024];
    ss[t] = sum;
    __syncthreads();
#pragma unroll
    for (int s2 = 512; s2; s2 >>= 1) {
        if (t < s2) ss[t] += ss[t + s2];
        __syncthreads();
    }
    if (t == 0) *out = ss[0] * (1.0f / (float)(BB * MM));
}

extern "C" void kernel_launch(void* const* d_in, const int* in_sizes, int n_in,
                              void* d_out, int out_size) {
    const float* keypoints = (const float*)d_in[0];  // [B,3,M]
    const float* pc        = (const float*)d_in[1];  // [B,3,N]
    float* out             = (float*)d_out;          // scalar

    (void)in_sizes; (void)n_in; (void)out_size;

    pack_kernel<<<(BB * NN + 255) / 256, 256>>>(pc);

    dim3 grid(NCHUNKS, MM / KM, BB);
    min_kernel<<<grid, NTHREADS>>>(keypoints);

    reduce_kernel<<<1, 1024>>>(keypoints, out);
}